// round 11
// baseline (speedup 1.0000x reference)
#include <cuda_runtime.h>
#include <cuda_bf16.h>
#include <mma.h>
#include <math.h>
#include <stdint.h>

using namespace nvcuda;

#define N_ATOMS 20000
#define N_EDGES 320000
#define FDIM    64
#define LT2     79       // ceil(20000/256) row-tiles for k_lin
#define ETILES  2500     // N_EDGES / 128

typedef unsigned long long ull;
typedef __nv_bfloat16 bf16;

// ---------------- device scratch (static, no allocations) ----------------
__device__ float g_comps[N_ATOMS * 9 * FDIM];   // Y (lin-pre out), [n][c][g]
__device__ float g_msg  [N_ATOMS * 9 * FDIM];   // messages [n][c][g]; later dX
__device__ float g_cfn  [9 * FDIM * N_ATOMS];   // comps in [c][f][n]
__device__ float g_rfv  [N_EDGES * 192];        // edge radial feats [e][k][f]
__device__ bf16  g_h1h[(size_t)N_EDGES * 128];  // h1 hi
__device__ bf16  g_h1l[(size_t)N_EDGES * 128];  // h1 lo
__device__ int   g_cnt [N_ATOMS];
__device__ int   g_off [N_ATOMS + 1];
__device__ int   g_cur [N_ATOMS];
__device__ int   g_slot[N_EDGES];

// ---------------- generic helpers ----------------
__device__ __forceinline__ ull pack2(float x, float y) {
    ull r; asm("mov.b64 %0, {%1,%2};" : "=l"(r) : "f"(x), "f"(y)); return r;
}
__device__ __forceinline__ void unpack2(ull v, float& x, float& y) {
    asm("mov.b64 {%0,%1}, %2;" : "=f"(x), "=f"(y) : "l"(v));
}
__device__ __forceinline__ ull fma2(ull a, ull b, ull c) {
    ull d; asm("fma.rn.f32x2 %0, %1, %2, %3;" : "=l"(d) : "l"(a), "l"(b), "l"(c)); return d;
}
__device__ __forceinline__ float siluf(float x) {
    return __fdividef(x, 1.0f + __expf(-x));
}
__device__ __forceinline__ float bfround(float v) {
    return __bfloat162float(__float2bfloat16(v));
}
// comps order: 0:i  1:a01 2:a02 3:a12  4:s00 5:s01 6:s02 7:s11 8:s12
__device__ __forceinline__ void recon(const float* c, float* T) {
    T[0] = c[0] + c[4];  T[1] = c[1] + c[5];  T[2] = c[2] + c[6];
    T[3] = c[5] - c[1];  T[4] = c[0] + c[7];  T[5] = c[3] + c[8];
    T[6] = c[6] - c[2];  T[7] = c[8] - c[3];  T[8] = c[0] - c[4] - c[7];
}
__device__ __forceinline__ void madd3(const float* A, const float* B, float* P) {
#pragma unroll
    for (int i = 0; i < 3; i++)
#pragma unroll
        for (int j = 0; j < 3; j++) {
            float s = P[i * 3 + j];
#pragma unroll
            for (int k = 0; k < 3; k++) s += A[i * 3 + k] * B[k * 3 + j];
            P[i * 3 + j] = s;
        }
}
__device__ __forceinline__ void decomp(const float* P, float* c) {
    float dm = (P[0] + P[4] + P[8]) * (1.0f / 3.0f);
    c[0] = dm;
    c[1] = 0.5f * (P[1] - P[3]);
    c[2] = 0.5f * (P[2] - P[6]);
    c[3] = 0.5f * (P[5] - P[7]);
    c[4] = P[0] - dm;
    c[5] = 0.5f * (P[1] + P[3]);
    c[6] = 0.5f * (P[2] + P[6]);
    c[7] = P[4] - dm;
    c[8] = 0.5f * (P[5] + P[7]);
}

// ============================================================================
// K_mlp_a: layers 0+1 via wmma bf16 (bf16x3 split), one 128-edge tile per block
// smem layout (bytes):
//   0      RFh [128][40] bf16 (10240)
//   10240  RFl            (10240)
//   20480  W0h [64][40]   (5120)
//   25600  W0l            (5120)
//   30720  H0  f32 [128][68] (34816)   -- L0 staging; region 0..65535 reused as
//                                         ST1 f32 [128][68] @0 for L1 staging
//   65536  W1h [128][72]  (18432)
//   83968  W1l            (18432)
//   102400 A1h [128][72]  (18432)
//   120832 A1l            (18432)
//   139264 sB0 (64 f32), 139520 sB1 (128 f32)  -> total 140032
// ============================================================================
__global__ void __launch_bounds__(256) k_mlp_a(
    const float* __restrict__ rf,
    const float* __restrict__ W0, const float* __restrict__ b0,
    const float* __restrict__ W1, const float* __restrict__ b1) {
    extern __shared__ char smb[];
    bf16* RFh = (bf16*)(smb + 0);
    bf16* RFl = (bf16*)(smb + 10240);
    bf16* W0h = (bf16*)(smb + 20480);
    bf16* W0l = (bf16*)(smb + 25600);
    float* H0  = (float*)(smb + 30720);
    float* ST1 = (float*)(smb + 0);
    bf16* W1h = (bf16*)(smb + 65536);
    bf16* W1l = (bf16*)(smb + 83968);
    bf16* A1h = (bf16*)(smb + 102400);
    bf16* A1l = (bf16*)(smb + 120832);
    float* sB0 = (float*)(smb + 139264);
    float* sB1 = (float*)(smb + 139520);
    int t = threadIdx.x, w = t >> 5;
    int E0 = blockIdx.x * 128;

    for (int i = t; i < 4096; i += 256) {     // rf 128x32
        int e = i >> 5, k = i & 31;
        float v = rf[(E0 + e) * 32 + k];
        float h = bfround(v);
        RFh[e * 40 + k] = __float2bfloat16(v);
        RFl[e * 40 + k] = __float2bfloat16(v - h);
    }
    for (int i = t; i < 2048; i += 256) {     // W0 64x32
        int r = i >> 5, k = i & 31;
        float v = W0[i];
        float h = bfround(v);
        W0h[r * 40 + k] = __float2bfloat16(v);
        W0l[r * 40 + k] = __float2bfloat16(v - h);
    }
    for (int i = t; i < 8192; i += 256) {     // W1 128x64
        int r = i >> 6, k = i & 63;
        float v = W1[i];
        float h = bfround(v);
        W1h[r * 72 + k] = __float2bfloat16(v);
        W1l[r * 72 + k] = __float2bfloat16(v - h);
    }
    if (t < 64) sB0[t] = b0[t];
    if (t < 128) sB1[t] = b1[t];
    __syncthreads();

    // ---- L0: [128,64] = A[128,32] @ W0^T ----
    {
        wmma::fragment<wmma::accumulator, 16, 16, 16, float> acc[4];
#pragma unroll
        for (int n = 0; n < 4; n++) wmma::fill_fragment(acc[n], 0.0f);
#pragma unroll 1
        for (int p = 0; p < 3; p++) {
            const bf16* Ab = (p == 2) ? RFl : RFh;
            const bf16* Bb = (p == 1) ? W0l : W0h;
#pragma unroll
            for (int k = 0; k < 2; k++) {
                wmma::fragment<wmma::matrix_a, 16, 16, 16, bf16, wmma::row_major> af;
                wmma::load_matrix_sync(af, Ab + (16 * w) * 40 + 16 * k, 40);
#pragma unroll
                for (int n = 0; n < 4; n++) {
                    wmma::fragment<wmma::matrix_b, 16, 16, 16, bf16, wmma::col_major> bfr;
                    wmma::load_matrix_sync(bfr, Bb + (16 * n) * 40 + 16 * k, 40);
                    wmma::mma_sync(acc[n], af, bfr, acc[n]);
                }
            }
        }
#pragma unroll
        for (int n = 0; n < 4; n++)
            wmma::store_matrix_sync(H0 + (16 * w) * 68 + 16 * n, acc[n], 68, wmma::mem_row_major);
    }
    __syncthreads();
    for (int i = t; i < 8192; i += 256) {     // silu + split -> A1
        int e = i >> 6, k = i & 63;
        float v = siluf(H0[e * 68 + k] + sB0[k]);
        float h = bfround(v);
        A1h[e * 72 + k] = __float2bfloat16(v);
        A1l[e * 72 + k] = __float2bfloat16(v - h);
    }
    __syncthreads();

    // ---- L1: [128,128] = A1[128,64] @ W1^T ----
    wmma::fragment<wmma::accumulator, 16, 16, 16, float> acc1[8];
#pragma unroll
    for (int n = 0; n < 8; n++) wmma::fill_fragment(acc1[n], 0.0f);
#pragma unroll 1
    for (int p = 0; p < 3; p++) {
        const bf16* Ab = (p == 2) ? A1l : A1h;
        const bf16* Bb = (p == 1) ? W1l : W1h;
#pragma unroll
        for (int k = 0; k < 4; k++) {
            wmma::fragment<wmma::matrix_a, 16, 16, 16, bf16, wmma::row_major> af;
            wmma::load_matrix_sync(af, Ab + (16 * w) * 72 + 16 * k, 72);
#pragma unroll
            for (int n = 0; n < 8; n++) {
                wmma::fragment<wmma::matrix_b, 16, 16, 16, bf16, wmma::col_major> bfr;
                wmma::load_matrix_sync(bfr, Bb + (16 * n) * 72 + 16 * k, 72);
                wmma::mma_sync(acc1[n], af, bfr, acc1[n]);
            }
        }
    }
#pragma unroll 1
    for (int half = 0; half < 2; half++) {
        __syncthreads();                      // ST1 region free (overwrites RF/W0/H0)
#pragma unroll
        for (int n = 0; n < 4; n++)
            wmma::store_matrix_sync(ST1 + (16 * w) * 68 + 16 * n, acc1[half * 4 + n],
                                    68, wmma::mem_row_major);
        __syncthreads();
        for (int i = t; i < 8192; i += 256) {
            int e = i >> 6, k = i & 63;
            int col = half * 64 + k;
            float v = siluf(ST1[e * 68 + k] + sB1[col]);
            float h = bfround(v);
            size_t gb = (size_t)(E0 + e) * 128 + col;
            g_h1h[gb] = __float2bfloat16(v);
            g_h1l[gb] = __float2bfloat16(v - h);
        }
    }
}

// ============================================================================
// K_mlp_b: layer 2 via wmma + cutoff epilogue
// smem: 0 AH [128][136] bf16 (34816); 34816 AL; 69632 W2h [192][136] (52224);
//       121856 W2l; 174080 ST f32 [128][68] (34816); 208896 sB2 (192 f);
//       209664 sC (128 f) -> total 210176
// W2 rows stored permuted: row r = cc*64+f  <->  neuron 3f+cc
// ============================================================================
__global__ void __launch_bounds__(256) k_mlp_b(
    const float* __restrict__ dij,
    const float* __restrict__ W2, const float* __restrict__ b2) {
    extern __shared__ char smb[];
    bf16* AH  = (bf16*)(smb + 0);
    bf16* AL  = (bf16*)(smb + 34816);
    bf16* W2h = (bf16*)(smb + 69632);
    bf16* W2l = (bf16*)(smb + 121856);
    float* ST  = (float*)(smb + 174080);
    float* sB2 = (float*)(smb + 208896);
    float* sC  = (float*)(smb + 209664);
    int t = threadIdx.x, w = t >> 5;
    int E0 = blockIdx.x * 128;

    for (int i = t; i < 16384; i += 256) {    // h1 128x128
        int e = i >> 7, k = i & 127;
        size_t gb = (size_t)(E0 + e) * 128 + k;
        AH[e * 136 + k] = g_h1h[gb];
        AL[e * 136 + k] = g_h1l[gb];
    }
    for (int i = t; i < 24576; i += 256) {    // W2 192x128, rows permuted
        int r = i >> 7, k = i & 127;
        int cc = r >> 6, f = r & 63;
        float v = W2[(3 * f + cc) * 128 + k];
        float h = bfround(v);
        W2h[r * 136 + k] = __float2bfloat16(v);
        W2l[r * 136 + k] = __float2bfloat16(v - h);
    }
    if (t < 192) {
        int cc = t >> 6, f = t & 63;
        sB2[t] = b2[3 * f + cc];
    }
    if (t < 128) {
        float d = dij[E0 + t];
        sC[t] = (d < 1.0f) ? (0.5f * (cospif(d) + 1.0f)) : 0.0f;
    }
    __syncthreads();

    wmma::fragment<wmma::accumulator, 16, 16, 16, float> acc[12];
#pragma unroll
    for (int n = 0; n < 12; n++) wmma::fill_fragment(acc[n], 0.0f);
#pragma unroll 1
    for (int p = 0; p < 3; p++) {
        const bf16* Ab = (p == 2) ? AL : AH;
        const bf16* Bb = (p == 1) ? W2l : W2h;
#pragma unroll 1
        for (int k = 0; k < 8; k++) {
            wmma::fragment<wmma::matrix_a, 16, 16, 16, bf16, wmma::row_major> af;
            wmma::load_matrix_sync(af, Ab + (16 * w) * 136 + 16 * k, 136);
#pragma unroll
            for (int n = 0; n < 12; n++) {
                wmma::fragment<wmma::matrix_b, 16, 16, 16, bf16, wmma::col_major> bfr;
                wmma::load_matrix_sync(bfr, Bb + (16 * n) * 136 + 16 * k, 136);
                wmma::mma_sync(acc[n], af, bfr, acc[n]);
            }
        }
    }

#pragma unroll 1
    for (int cc = 0; cc < 3; cc++) {
        __syncthreads();
#pragma unroll
        for (int n = 0; n < 4; n++)
            wmma::store_matrix_sync(ST + (16 * w) * 68 + 16 * n, acc[cc * 4 + n],
                                    68, wmma::mem_row_major);
        __syncthreads();
        for (int i = t; i < 8192; i += 256) {
            int e = i >> 6, f = i & 63;
            float v = siluf(ST[e * 68 + f] + sB2[cc * 64 + f]) * sC[e];
            g_rfv[(size_t)(E0 + e) * 192 + cc * 64 + f] = v;
        }
    }
}

// ============== K_decomp: normalize X, decompose -> g_cfn [c][f][n] ==============
__global__ void __launch_bounds__(256) k_decomp(const float* __restrict__ X) {
    extern __shared__ float sT[];        // 576*33
    int t = threadIdx.x;
    int n0 = blockIdx.x * 32;
#pragma unroll 1
    for (int p = 0; p < 8; p++) {
        int a = p * 4 + (t >> 6);
        int f = t & 63;
        int n = n0 + a;
        const float* x = X + n * 576 + f * 9;
        float xv[9]; float tn = 0.f;
#pragma unroll
        for (int j = 0; j < 9; j++) { xv[j] = x[j]; tn += xv[j] * xv[j]; }
        float inv = 1.f / (tn + 1.f);
#pragma unroll
        for (int j = 0; j < 9; j++) xv[j] *= inv;
        float c9[9]; decomp(xv, c9);
#pragma unroll
        for (int c = 0; c < 9; c++) sT[(c * 64 + f) * 33 + a] = c9[c];
    }
    __syncthreads();
    for (int i = t; i < 18432; i += 256) {
        int a = i & 31, cf = i >> 5;
        g_cfn[cf * 20000 + n0 + a] = sT[cf * 33 + a];
    }
}

// ============== K_lin: per-c GEMM, 256-row tiles, (w,w)-dup weights ==============
__global__ void __launch_bounds__(256) k_lin(const float* __restrict__ Wt, int post) {
    extern __shared__ ull sml[];
    ull*   sW = sml;                     // 4096
    float* sA = (float*)(sml + 4096);    // 64*264
    int t = threadIdx.x;
    int c  = blockIdx.x / LT2;
    int tb = blockIdx.x % LT2;
    int m = (c == 0) ? 0 : (c < 4) ? 1 : 2;
    const float* W = Wt + (post ? 3 : 0) * 4096 + m * 4096;
    for (int i = t; i < 4096; i += 256) {
        int k = i >> 6, g = i & 63;
        float w = W[g * 64 + k];
        sW[i] = pack2(w, w);
    }
    int n0 = tb * 256;
    int rows = N_ATOMS - n0; if (rows > 256) rows = 256;
    for (int i = t; i < 16384; i += 256) {
        int f = i >> 8, nl = i & 255;
        sA[f * 264 + nl] = (nl < rows) ? g_cfn[(c * 64 + f) * 20000 + n0 + nl] : 0.f;
    }
    __syncthreads();
    int r0 = t >> 4;
    int c0 = t & 15;
    ull acc[4][8];
#pragma unroll
    for (int j = 0; j < 4; j++)
#pragma unroll
        for (int p = 0; p < 8; p++) acc[j][p] = 0;
#pragma unroll 2
    for (int k = 0; k < 64; k++) {
        const float* row = sA + k * 264;
        ulonglong2 hA = *(const ulonglong2*)&row[8 * r0];
        ulonglong2 hB = *(const ulonglong2*)&row[8 * r0 + 4];
        ulonglong2 hC = *(const ulonglong2*)&row[128 + 8 * r0];
        ulonglong2 hD = *(const ulonglong2*)&row[128 + 8 * r0 + 4];
        ulonglong2 wA = *(const ulonglong2*)(sW + k * 64 + 4 * c0);
        ulonglong2 wB = *(const ulonglong2*)(sW + k * 64 + 4 * c0 + 2);
        ull w0 = wA.x, w1 = wA.y, w2 = wB.x, w3 = wB.y;
        ull h[8] = {hA.x, hA.y, hB.x, hB.y, hC.x, hC.y, hD.x, hD.y};
#pragma unroll
        for (int p = 0; p < 8; p++) {
            acc[0][p] = fma2(w0, h[p], acc[0][p]);
            acc[1][p] = fma2(w1, h[p], acc[1][p]);
            acc[2][p] = fma2(w2, h[p], acc[2][p]);
            acc[3][p] = fma2(w3, h[p], acc[3][p]);
        }
    }
    __syncthreads();
    float* sO = sA;
#pragma unroll
    for (int j = 0; j < 4; j++) {
        int g = 4 * c0 + j;
#pragma unroll
        for (int p = 0; p < 8; p++) {
            int rb = (p < 4) ? (8 * r0 + 2 * p) : (128 + 8 * r0 + 2 * (p - 4));
            float x, y; unpack2(acc[j][p], x, y);
            sO[rb * 66 + g]       = x;
            sO[(rb + 1) * 66 + g] = y;
        }
    }
    __syncthreads();
    float* outp = post ? g_msg : g_comps;
    for (int i = t; i < 16384; i += 256) {
        int nl = i >> 6, g = i & 63;
        if (nl < rows) outp[(n0 + nl) * 576 + c * 64 + g] = sO[nl * 66 + g];
    }
}

// ============== CSR build ==============
__global__ void k_zero() {
    int i = blockIdx.x * blockDim.x + threadIdx.x;
    if (i < N_ATOMS) g_cnt[i] = 0;
}
__global__ void k_hist(const int* __restrict__ pr) {
    int e = blockIdx.x * blockDim.x + threadIdx.x;
    if (e < N_EDGES) atomicAdd(&g_cnt[pr[e]], 1);
}
__global__ void k_scan() {
    __shared__ int s[1024];
    const int CH = 20;
    int t = threadIdx.x;
    int base = t * CH;
    int local[CH];
    int sum = 0;
#pragma unroll
    for (int i = 0; i < CH; i++) {
        int idx = base + i;
        int v = (idx < N_ATOMS) ? g_cnt[idx] : 0;
        local[i] = sum; sum += v;
    }
    s[t] = sum; __syncthreads();
    for (int d = 1; d < 1024; d <<= 1) {
        int v = (t >= d) ? s[t - d] : 0;
        __syncthreads();
        s[t] += v;
        __syncthreads();
    }
    int pre = (t == 0) ? 0 : s[t - 1];
#pragma unroll
    for (int i = 0; i < CH; i++) {
        int idx = base + i;
        if (idx < N_ATOMS) { int o = pre + local[i]; g_off[idx] = o; g_cur[idx] = o; }
    }
    if (t == 1023) g_off[N_ATOMS] = s[1023];
}
__global__ void k_scatter(const int* __restrict__ pr) {
    int e = blockIdx.x * blockDim.x + threadIdx.x;
    if (e < N_EDGES) {
        int pos = atomicAdd(&g_cur[pr[e]], 1);
        g_slot[pos] = e;
    }
}

// ============== K3: dst-centric segment reduction ==============
__global__ void k_reduce(const int* __restrict__ pr) {
    int lane = threadIdx.x & 31;
    int wid = threadIdx.x >> 5;
    for (int n = blockIdx.x * (blockDim.x >> 5) + wid; n < N_ATOMS;
         n += gridDim.x * (blockDim.x >> 5)) {
        float2 acc[9];
#pragma unroll
        for (int c = 0; c < 9; c++) acc[c] = make_float2(0.f, 0.f);
        int beg = g_off[n], end = g_off[n + 1];
        for (int j = beg; j < end; j++) {
            int e = g_slot[j];
            int s = pr[N_EDGES + e];
            const float2* rp = (const float2*)(g_rfv + (size_t)e * 192);
            float2 r0 = rp[lane];
            float2 r1 = rp[32 + lane];
            float2 r2 = rp[64 + lane];
            const float2* cp = (const float2*)(g_comps + s * 576);
#pragma unroll
            for (int c = 0; c < 9; c++) {
                float2 v = cp[c * 32 + lane];
                float2 sc = (c == 0) ? r0 : (c < 4) ? r1 : r2;
                acc[c].x += sc.x * v.x;
                acc[c].y += sc.y * v.y;
            }
        }
        float2* mp = (float2*)(g_msg + n * 576);
#pragma unroll
        for (int c = 0; c < 9; c++) mp[c * 32 + lane] = acc[c];
    }
}

// ============== K_prod: q*(MY+YM), decompose, normalize -> g_cfn ==============
__global__ void __launch_bounds__(256) k_prod(const float* __restrict__ chg) {
    extern __shared__ float sT[];
    int t = threadIdx.x;
    int n0 = blockIdx.x * 32;
#pragma unroll 1
    for (int p = 0; p < 8; p++) {
        int a = p * 4 + (t >> 6);
        int g = t & 63;
        int n = n0 + a;
        float q = 1.0f + 0.1f * chg[n];
        float cm[9], cy[9];
#pragma unroll
        for (int c = 0; c < 9; c++) {
            cm[c] = g_msg[n * 576 + c * 64 + g];
            cy[c] = g_comps[n * 576 + c * 64 + g];
        }
        float M[9], Y[9];
        recon(cm, M); recon(cy, Y);
        float P[9];
#pragma unroll
        for (int j = 0; j < 9; j++) P[j] = 0.f;
        madd3(M, Y, P);
        madd3(Y, M, P);
        float tn2 = 0.f;
#pragma unroll
        for (int j = 0; j < 9; j++) { P[j] *= q; tn2 += P[j] * P[j]; }
        float invn = 1.f / (tn2 + 1.f);
        float c9[9]; decomp(P, c9);
#pragma unroll
        for (int c = 0; c < 9; c++) sT[(c * 64 + g) * 33 + a] = c9[c] * invn;
    }
    __syncthreads();
    for (int i = t; i < 18432; i += 256) {
        int a = i & 31, cf = i >> 5;
        g_cfn[cf * 20000 + n0 + a] = sT[cf * 33 + a];
    }
}

// ============== K_finish: X update ==============
__global__ void __launch_bounds__(256) k_finish(const float* __restrict__ X,
                                                const float* __restrict__ chg,
                                                float* __restrict__ out) {
    int idx = blockIdx.x * 256 + threadIdx.x;
    if (idx >= N_ATOMS * 64) return;
    int n = idx >> 6, g = idx & 63;
    float q = 1.0f + 0.1f * chg[n];
    const float* x = X + n * 576 + g * 9;
    float xv[9]; float tn = 0.f;
#pragma unroll
    for (int j = 0; j < 9; j++) { xv[j] = x[j]; tn += xv[j] * xv[j]; }
    float inv = 1.f / (tn + 1.f);
#pragma unroll
    for (int j = 0; j < 9; j++) xv[j] *= inv;
    float cd[9];
#pragma unroll
    for (int c = 0; c < 9; c++) cd[c] = g_msg[n * 576 + c * 64 + g];
    float dx[9]; recon(cd, dx);
    float dd[9];
#pragma unroll
    for (int j = 0; j < 9; j++) dd[j] = 0.f;
    madd3(dx, dx, dd);
#pragma unroll
    for (int j = 0; j < 9; j++)
        out[n * 576 + g * 9 + j] = xv[j] + dx[j] + q * dd[j];
}

// ---------------- launch ----------------
extern "C" void kernel_launch(void* const* d_in, const int* in_sizes, int n_in,
                              void* d_out, int out_size) {
    const float* X   = (const float*)d_in[0];
    const int*   pr  = (const int*)d_in[1];
    const float* dij = (const float*)d_in[2];
    const float* rf  = (const float*)d_in[3];
    const float* chg = (const float*)d_in[4];
    const float* W0  = (const float*)d_in[5];
    const float* b0  = (const float*)d_in[6];
    const float* W1  = (const float*)d_in[7];
    const float* b1  = (const float*)d_in[8];
    const float* W2  = (const float*)d_in[9];
    const float* b2  = (const float*)d_in[10];
    const float* Wt  = (const float*)d_in[11];
    float* out = (float*)d_out;

    const int smem_a   = 140032;
    const int smem_b   = 210176;
    const int smem_tr  = 576 * 33 * 4;                  // 76032
    const int smem_lin = 4096 * 8 + 16896 * 4;          // 100352
    cudaFuncSetAttribute(k_mlp_a, cudaFuncAttributeMaxDynamicSharedMemorySize, smem_a);
    cudaFuncSetAttribute(k_mlp_b, cudaFuncAttributeMaxDynamicSharedMemorySize, smem_b);
    cudaFuncSetAttribute(k_decomp, cudaFuncAttributeMaxDynamicSharedMemorySize, smem_tr);
    cudaFuncSetAttribute(k_prod,   cudaFuncAttributeMaxDynamicSharedMemorySize, smem_tr);
    cudaFuncSetAttribute(k_lin,    cudaFuncAttributeMaxDynamicSharedMemorySize, smem_lin);

    k_zero<<<(N_ATOMS + 255) / 256, 256>>>();
    k_hist<<<(N_EDGES + 255) / 256, 256>>>(pr);
    k_scan<<<1, 1024>>>();
    k_mlp_a<<<ETILES, 256, smem_a>>>(rf, W0, b0, W1, b1);   // slot 4: profiled
    k_mlp_b<<<ETILES, 256, smem_b>>>(dij, W2, b2);
    k_scatter<<<(N_EDGES + 255) / 256, 256>>>(pr);
    k_decomp<<<625, 256, smem_tr>>>(X);
    k_lin<<<9 * LT2, 256, smem_lin>>>(Wt, 0);
    k_reduce<<<2500, 256>>>(pr);
    k_prod<<<625, 256, smem_tr>>>(chg);
    k_lin<<<9 * LT2, 256, smem_lin>>>(Wt, 1);
    k_finish<<<(N_ATOMS * 64 + 255) / 256, 256>>>(X, chg, out);
}